// round 1
// baseline (speedup 1.0000x reference)
#include <cuda_runtime.h>
#include <math_constants.h>
#include <stdint.h>

#define NB    8
#define NPTS  4096
#define KNN   20
#define CH    64
#define NSAMP (NB*NPTS*KNN)      // 655360
#define BN_EPS 1e-5
#define SLOPE  0.2f

// ---------------- device scratch (no allocations allowed) ----------------
__device__ float4 g_packed[NB*NPTS];                 // (x,y,z,|p|^2)
__device__ float  g_E8[(size_t)NSAMP*8];             // edge feats padded to 8
__device__ double g_S1[6];
__device__ double g_S2[21];
__device__ float  g_W1f[CH*6];
__device__ float  g_c1[CH];
__device__ double g_h2sum[CH];
__device__ double g_h2sq[CH];
__device__ float  g_a2[CH], g_c2[CH];
__device__ float  g_hmax[(size_t)NB*NPTS*CH];
__device__ float  g_hmin[(size_t)NB*NPTS*CH];

// ---------------- K0: pack points + zero accumulators ----------------
__global__ void k0_pack(const float* __restrict__ a) {
    int t = blockIdx.x*blockDim.x + threadIdx.x;     // 0..32767
    int b = t / NPTS, n = t % NPTS;
    const float* ab = a + (size_t)b*3*NPTS;
    float x = ab[n], y = ab[NPTS+n], z = ab[2*NPTS+n];
    float sq = fmaf(z,z, fmaf(y,y, x*x));
    g_packed[t] = make_float4(x,y,z,sq);
    if (blockIdx.x == 0) {
        int i = threadIdx.x;
        if (i < 6)  g_S1[i] = 0.0;
        if (i < 21) g_S2[i] = 0.0;
        if (i < CH) { g_h2sum[i] = 0.0; g_h2sq[i] = 0.0; }
    }
}

// ---------------- K1: exact KNN (top-20 smallest d, jax tie order) ------
// d = sq_i + sq_j - 2*dot(p_i,p_j). Ascending-index scan with strict '<'
// reproduces top_k's (value,index) lexicographic tie-breaking exactly.
__global__ void __launch_bounds__(64) k1_knn() {
    int tid = blockIdx.x*blockDim.x + threadIdx.x;   // 512 blocks x 64
    int b = tid / NPTS; int i = tid % NPTS;
    const float4* pts = &g_packed[b*NPTS];
    float4 pi = pts[i];
    float n2x = -2.f*pi.x, n2y = -2.f*pi.y, n2z = -2.f*pi.z;

    float dl[KNN]; int il[KNN];
    #pragma unroll
    for (int t = 0; t < KNN; t++) { dl[t] = CUDART_INF_F; il[t] = 0; }

    for (int j = 0; j < NPTS; j += 4) {
        #pragma unroll
        for (int u = 0; u < 4; u++) {
            float4 pj = __ldg(&pts[j+u]);
            float d = fmaf(n2z, pj.z, fmaf(n2y, pj.y, fmaf(n2x, pj.x, pj.w)));
            d += pi.w;
            if (d < dl[KNN-1]) {                     // guarded bubble insert
                int jj = j + u;
                #pragma unroll
                for (int t = 0; t < KNN; t++) {
                    bool p = d < dl[t];
                    float od = dl[t]; int oi = il[t];
                    dl[t] = p ? d  : od;  il[t] = p ? jj : oi;
                    d     = p ? od : d;   jj    = p ? oi : jj;
                }
            }
        }
    }
    // emit edge features [diff(3), pts(3), 0, 0]
    float4* E = (float4*)(g_E8 + (size_t)tid*KNN*8);
    #pragma unroll
    for (int t = 0; t < KNN; t++) {
        float4 pj = pts[il[t]];
        E[t*2+0] = make_float4(pj.x-pi.x, pj.y-pi.y, pj.z-pi.z, pi.x);
        E[t*2+1] = make_float4(pi.y, pi.z, 0.f, 0.f);
    }
}

// ---------------- K2: 1st+2nd moments of edge features ----------------
__global__ void k2_mom() {
    int t = blockIdx.x*blockDim.x + threadIdx.x;     // 512x256 -> 5 samples each
    float s1[6]; float s2[21];
    #pragma unroll
    for (int c = 0; c < 6; c++)  s1[c] = 0.f;
    #pragma unroll
    for (int q = 0; q < 21; q++) s2[q] = 0.f;

    #pragma unroll
    for (int s = 0; s < 5; s++) {
        size_t idx = (size_t)(t*5 + s) * 8;
        float4 v0 = *(const float4*)&g_E8[idx];
        float4 v1 = *(const float4*)&g_E8[idx+4];
        float x[6] = {v0.x, v0.y, v0.z, v0.w, v1.x, v1.y};
        #pragma unroll
        for (int c = 0; c < 6; c++) s1[c] += x[c];
        int q = 0;
        #pragma unroll
        for (int c1 = 0; c1 < 6; c1++)
            #pragma unroll
            for (int c2 = c1; c2 < 6; c2++) { s2[q] = fmaf(x[c1], x[c2], s2[q]); q++; }
    }
    #pragma unroll
    for (int o = 16; o > 0; o >>= 1) {
        #pragma unroll
        for (int c = 0; c < 6; c++)  s1[c] += __shfl_xor_sync(~0u, s1[c], o);
        #pragma unroll
        for (int q = 0; q < 21; q++) s2[q] += __shfl_xor_sync(~0u, s2[q], o);
    }
    if ((threadIdx.x & 31) == 0) {
        #pragma unroll
        for (int c = 0; c < 6; c++)  atomicAdd(&g_S1[c], (double)s1[c]);
        #pragma unroll
        for (int q = 0; q < 21; q++) atomicAdd(&g_S2[q], (double)s2[q]);
    }
}

// ---------------- F1: fold BN1 into W1 (mean/var of W1x from moments) ---
__global__ void f1_fold(const float* __restrict__ W1, const float* __restrict__ g1,
                        const float* __restrict__ b1) {
    int o = threadIdx.x; if (o >= CH) return;
    double M = (double)NSAMP;
    double m1[6];
    for (int c = 0; c < 6; c++) m1[c] = g_S1[c] / M;
    double E2[6][6]; int q = 0;
    for (int c1 = 0; c1 < 6; c1++)
        for (int c2 = c1; c2 < 6; c2++) { double v = g_S2[q++] / M; E2[c1][c2] = v; E2[c2][c1] = v; }
    double w[6];
    for (int c = 0; c < 6; c++) w[c] = (double)W1[o*6 + c];
    double mean = 0.0;
    for (int c = 0; c < 6; c++) mean += w[c]*m1[c];
    double e2 = 0.0;
    for (int c1 = 0; c1 < 6; c1++) { double acc = 0.0;
        for (int c2 = 0; c2 < 6; c2++) acc += w[c2]*E2[c1][c2];
        e2 += w[c1]*acc; }
    double var = e2 - mean*mean;
    double a = (double)g1[o] / sqrt(var + BN_EPS);
    g_c1[o] = (float)((double)b1[o] - mean*a);
    for (int c = 0; c < 6; c++) g_W1f[o*6 + c] = (float)(a*w[c]);
}

// ---------------- K3: fused MLP + BN2 stats + max/min over K -----------
#define PPB 16
__global__ void __launch_bounds__(256) k3_mlp(const float* __restrict__ W2) {
    __shared__ float sW2T[CH*CH];        // [c][o]
    __shared__ float y1s[CH*21];         // [u][k], pitch 21
    __shared__ float redm[256], redn[256];
    int t = threadIdx.x;
    for (int s = t; s < CH*CH; s += 256) { int c = s / CH, o = s % CH; sW2T[s] = W2[o*CH + c]; }
    int u  = t % CH;                     // layer1-out channel / layer2-out channel
    int kq = t / CH;                     // 0..3, 5 k's each
    float w1r[6];
    #pragma unroll
    for (int c = 0; c < 6; c++) w1r[c] = g_W1f[u*6 + c];
    float c1v = g_c1[u];
    float accs = 0.f, accq = 0.f;
    __syncthreads();

    for (int pp = 0; pp < PPB; pp++) {
        int p = blockIdx.x*PPB + pp;     // global point index (b*NPTS+n)
        const float* Ep = g_E8 + (size_t)p*KNN*8;
        // phase A: y1 = lrelu(W1f x + c1)
        #pragma unroll
        for (int kk = 0; kk < 5; kk++) {
            int k = kq*5 + kk;
            float4 v0 = *(const float4*)&Ep[k*8];
            float4 v1 = *(const float4*)&Ep[k*8 + 4];
            float h = c1v;
            h = fmaf(w1r[0], v0.x, h);
            h = fmaf(w1r[1], v0.y, h);
            h = fmaf(w1r[2], v0.z, h);
            h = fmaf(w1r[3], v0.w, h);
            h = fmaf(w1r[4], v1.x, h);
            h = fmaf(w1r[5], v1.y, h);
            y1s[u*21 + k] = (h >= 0.f) ? h : SLOPE*h;
        }
        __syncthreads();
        // phase B: h2 = W2 y1 for this thread's (u, 5 k's)
        float h2[5];
        #pragma unroll
        for (int kk = 0; kk < 5; kk++) h2[kk] = 0.f;
        #pragma unroll 8
        for (int c = 0; c < CH; c++) {
            float w = sW2T[c*CH + u];
            const float* yr = &y1s[c*21 + kq*5];
            #pragma unroll
            for (int kk = 0; kk < 5; kk++) h2[kk] = fmaf(w, yr[kk], h2[kk]);
        }
        float mx = h2[0], mn = h2[0];
        #pragma unroll
        for (int kk = 0; kk < 5; kk++) {
            accs += h2[kk]; accq = fmaf(h2[kk], h2[kk], accq);
            mx = fmaxf(mx, h2[kk]); mn = fminf(mn, h2[kk]);
        }
        redm[t] = mx; redn[t] = mn;
        __syncthreads();
        if (kq == 0) {
            float fmx = fmaxf(fmaxf(redm[u], redm[u+64]), fmaxf(redm[u+128], redm[u+192]));
            float fmn = fminf(fminf(redn[u], redn[u+64]), fminf(redn[u+128], redn[u+192]));
            g_hmax[(size_t)p*CH + u] = fmx;
            g_hmin[(size_t)p*CH + u] = fmn;
        }
        __syncthreads();                 // also protects y1s/red reuse
    }
    // BN2 stats block reduction -> double atomics
    redm[t] = accs; redn[t] = accq;
    __syncthreads();
    if (t < CH) {
        atomicAdd(&g_h2sum[t], (double)(redm[t] + redm[t+64] + redm[t+128] + redm[t+192]));
        atomicAdd(&g_h2sq[t],  (double)(redn[t] + redn[t+64] + redn[t+128] + redn[t+192]));
    }
}

// ---------------- F2: finalize BN2 ----------------
__global__ void f2_fold(const float* __restrict__ g2, const float* __restrict__ b2) {
    int o = threadIdx.x; if (o >= CH) return;
    double M = (double)NSAMP;
    double m = g_h2sum[o] / M;
    double v = g_h2sq[o] / M - m*m;
    double a = (double)g2[o] / sqrt(v + BN_EPS);
    g_a2[o] = (float)a;
    g_c2[o] = (float)((double)b2[o] - m*a);
}

// ---------------- K5: BN2+lrelu (via monotone max/min trick) + transpose
__global__ void k5_out(float* __restrict__ out) {
    __shared__ float tile[32][33];
    int b = blockIdx.z;
    int n0 = blockIdx.x*32, o0 = blockIdx.y*32;
    int tx = threadIdx.x, ty = threadIdx.y;
    #pragma unroll
    for (int r = 0; r < 4; r++) {
        int n = n0 + ty + 8*r, o = o0 + tx;
        float a = g_a2[o], c = g_c2[o];
        size_t idx = ((size_t)(b*NPTS + n))*CH + o;
        float h = (a >= 0.f) ? g_hmax[idx] : g_hmin[idx];
        float v = fmaf(a, h, c);
        tile[ty + 8*r][tx] = (v >= 0.f) ? v : SLOPE*v;
    }
    __syncthreads();
    #pragma unroll
    for (int r = 0; r < 4; r++) {
        int o = o0 + ty + 8*r, n = n0 + tx;
        out[((size_t)(b*CH + o))*NPTS + n] = tile[tx][ty + 8*r];
    }
}

// ---------------- launch ----------------
extern "C" void kernel_launch(void* const* d_in, const int* in_sizes, int n_in,
                              void* d_out, int out_size) {
    const float* a  = (const float*)d_in[0];
    const float* W1 = (const float*)d_in[1];
    const float* g1 = (const float*)d_in[2];
    const float* b1 = (const float*)d_in[3];
    const float* W2 = (const float*)d_in[4];
    const float* g2 = (const float*)d_in[5];
    const float* b2 = (const float*)d_in[6];
    float* out = (float*)d_out;

    k0_pack<<<128, 256>>>(a);
    k1_knn<<<512, 64>>>();
    k2_mom<<<512, 256>>>();
    f1_fold<<<1, 64>>>(W1, g1, b1);
    k3_mlp<<<2048, 256>>>(W2);
    f2_fold<<<1, 64>>>(g2, b2);
    k5_out<<<dim3(128, 2, NB), dim3(32, 8)>>>(out);
}

// round 2
// speedup vs baseline: 1.0017x; 1.0017x over previous
#include <cuda_runtime.h>
#include <math_constants.h>
#include <stdint.h>

#define NB    8
#define NPTS  4096
#define KNN   20
#define CH    64
#define NSAMP (NB*NPTS*KNN)      // 655360
#define BN_EPS 1e-5
#define SLOPE  0.2f

// ---------------- device scratch (no allocations allowed) ----------------
__device__ float4 g_packed[NB*NPTS];                 // (x,y,z,|p|^2)
__device__ float  g_E8[(size_t)NSAMP*8];             // edge feats padded to 8
__device__ double g_S1[6];
__device__ double g_S2[21];
__device__ float  g_W1f[CH*6];
__device__ float  g_c1[CH];
__device__ double g_h2sum[CH];
__device__ double g_h2sq[CH];
__device__ float  g_a2[CH], g_c2[CH];
__device__ float  g_hmax[(size_t)NB*NPTS*CH];
__device__ float  g_hmin[(size_t)NB*NPTS*CH];

// ---------------- K0: pack points + zero accumulators ----------------
__global__ void k0_pack(const float* __restrict__ a) {
    int t = blockIdx.x*blockDim.x + threadIdx.x;     // 0..32767
    int b = t / NPTS, n = t % NPTS;
    const float* ab = a + (size_t)b*3*NPTS;
    float x = ab[n], y = ab[NPTS+n], z = ab[2*NPTS+n];
    float sq = fmaf(z,z, fmaf(y,y, x*x));
    g_packed[t] = make_float4(x,y,z,sq);
    if (blockIdx.x == 0) {
        int i = threadIdx.x;
        if (i < 6)  g_S1[i] = 0.0;
        if (i < 21) g_S2[i] = 0.0;
        if (i < CH) { g_h2sum[i] = 0.0; g_h2sq[i] = 0.0; }
    }
}

// ---------------- K1: exact KNN (top-20 smallest d, jax tie order) ------
// d = sq_i + sq_j - 2*dot(p_i,p_j). Ascending-index scan with strict '<'
// reproduces top_k's (value,index) lexicographic tie-breaking exactly.
__global__ void __launch_bounds__(64) k1_knn() {
    int tid = blockIdx.x*blockDim.x + threadIdx.x;   // 512 blocks x 64
    int b = tid / NPTS; int i = tid % NPTS;
    const float4* pts = &g_packed[b*NPTS];
    float4 pi = pts[i];
    float n2x = -2.f*pi.x, n2y = -2.f*pi.y, n2z = -2.f*pi.z;

    float dl[KNN]; int il[KNN];
    #pragma unroll
    for (int t = 0; t < KNN; t++) { dl[t] = CUDART_INF_F; il[t] = 0; }

    for (int j = 0; j < NPTS; j += 4) {
        #pragma unroll
        for (int u = 0; u < 4; u++) {
            float4 pj = __ldg(&pts[j+u]);
            float d = fmaf(n2z, pj.z, fmaf(n2y, pj.y, fmaf(n2x, pj.x, pj.w)));
            d += pi.w;
            if (d < dl[KNN-1]) {                     // guarded bubble insert
                int jj = j + u;
                #pragma unroll
                for (int t = 0; t < KNN; t++) {
                    bool p = d < dl[t];
                    float od = dl[t]; int oi = il[t];
                    dl[t] = p ? d  : od;  il[t] = p ? jj : oi;
                    d     = p ? od : d;   jj    = p ? oi : jj;
                }
            }
        }
    }
    // emit edge features [diff(3), pts(3), 0, 0]
    float4* E = (float4*)(g_E8 + (size_t)tid*KNN*8);
    #pragma unroll
    for (int t = 0; t < KNN; t++) {
        float4 pj = pts[il[t]];
        E[t*2+0] = make_float4(pj.x-pi.x, pj.y-pi.y, pj.z-pi.z, pi.x);
        E[t*2+1] = make_float4(pi.y, pi.z, 0.f, 0.f);
    }
}

// ---------------- K2: 1st+2nd moments of edge features ----------------
__global__ void k2_mom() {
    int t = blockIdx.x*blockDim.x + threadIdx.x;     // 512x256 -> 5 samples each
    float s1[6]; float s2[21];
    #pragma unroll
    for (int c = 0; c < 6; c++)  s1[c] = 0.f;
    #pragma unroll
    for (int q = 0; q < 21; q++) s2[q] = 0.f;

    #pragma unroll
    for (int s = 0; s < 5; s++) {
        size_t idx = (size_t)(t*5 + s) * 8;
        float4 v0 = *(const float4*)&g_E8[idx];
        float4 v1 = *(const float4*)&g_E8[idx+4];
        float x[6] = {v0.x, v0.y, v0.z, v0.w, v1.x, v1.y};
        #pragma unroll
        for (int c = 0; c < 6; c++) s1[c] += x[c];
        int q = 0;
        #pragma unroll
        for (int c1 = 0; c1 < 6; c1++)
            #pragma unroll
            for (int c2 = c1; c2 < 6; c2++) { s2[q] = fmaf(x[c1], x[c2], s2[q]); q++; }
    }
    #pragma unroll
    for (int o = 16; o > 0; o >>= 1) {
        #pragma unroll
        for (int c = 0; c < 6; c++)  s1[c] += __shfl_xor_sync(~0u, s1[c], o);
        #pragma unroll
        for (int q = 0; q < 21; q++) s2[q] += __shfl_xor_sync(~0u, s2[q], o);
    }
    if ((threadIdx.x & 31) == 0) {
        #pragma unroll
        for (int c = 0; c < 6; c++)  atomicAdd(&g_S1[c], (double)s1[c]);
        #pragma unroll
        for (int q = 0; q < 21; q++) atomicAdd(&g_S2[q], (double)s2[q]);
    }
}

// ---------------- F1: fold BN1 into W1 (mean/var of W1x from moments) ---
__global__ void f1_fold(const float* __restrict__ W1, const float* __restrict__ g1,
                        const float* __restrict__ b1) {
    int o = threadIdx.x; if (o >= CH) return;
    double M = (double)NSAMP;
    double m1[6];
    for (int c = 0; c < 6; c++) m1[c] = g_S1[c] / M;
    double E2[6][6]; int q = 0;
    for (int c1 = 0; c1 < 6; c1++)
        for (int c2 = c1; c2 < 6; c2++) { double v = g_S2[q++] / M; E2[c1][c2] = v; E2[c2][c1] = v; }
    double w[6];
    for (int c = 0; c < 6; c++) w[c] = (double)W1[o*6 + c];
    double mean = 0.0;
    for (int c = 0; c < 6; c++) mean += w[c]*m1[c];
    double e2 = 0.0;
    for (int c1 = 0; c1 < 6; c1++) { double acc = 0.0;
        for (int c2 = 0; c2 < 6; c2++) acc += w[c2]*E2[c1][c2];
        e2 += w[c1]*acc; }
    double var = e2 - mean*mean;
    double a = (double)g1[o] / sqrt(var + BN_EPS);
    g_c1[o] = (float)((double)b1[o] - mean*a);
    for (int c = 0; c < 6; c++) g_W1f[o*6 + c] = (float)(a*w[c]);
}

// ---------------- K3: fused MLP + BN2 stats + max/min over K -----------
#define PPB 16
__global__ void __launch_bounds__(256) k3_mlp(const float* __restrict__ W2) {
    __shared__ float sW2T[CH*CH];        // [c][o]
    __shared__ float y1s[CH*21];         // [u][k], pitch 21
    __shared__ float redm[256], redn[256];
    int t = threadIdx.x;
    for (int s = t; s < CH*CH; s += 256) { int c = s / CH, o = s % CH; sW2T[s] = W2[o*CH + c]; }
    int u  = t % CH;                     // layer1-out channel / layer2-out channel
    int kq = t / CH;                     // 0..3, 5 k's each
    float w1r[6];
    #pragma unroll
    for (int c = 0; c < 6; c++) w1r[c] = g_W1f[u*6 + c];
    float c1v = g_c1[u];
    float accs = 0.f, accq = 0.f;
    __syncthreads();

    for (int pp = 0; pp < PPB; pp++) {
        int p = blockIdx.x*PPB + pp;     // global point index (b*NPTS+n)
        const float* Ep = g_E8 + (size_t)p*KNN*8;
        // phase A: y1 = lrelu(W1f x + c1)
        #pragma unroll
        for (int kk = 0; kk < 5; kk++) {
            int k = kq*5 + kk;
            float4 v0 = *(const float4*)&Ep[k*8];
            float4 v1 = *(const float4*)&Ep[k*8 + 4];
            float h = c1v;
            h = fmaf(w1r[0], v0.x, h);
            h = fmaf(w1r[1], v0.y, h);
            h = fmaf(w1r[2], v0.z, h);
            h = fmaf(w1r[3], v0.w, h);
            h = fmaf(w1r[4], v1.x, h);
            h = fmaf(w1r[5], v1.y, h);
            y1s[u*21 + k] = (h >= 0.f) ? h : SLOPE*h;
        }
        __syncthreads();
        // phase B: h2 = W2 y1 for this thread's (u, 5 k's)
        float h2[5];
        #pragma unroll
        for (int kk = 0; kk < 5; kk++) h2[kk] = 0.f;
        #pragma unroll 8
        for (int c = 0; c < CH; c++) {
            float w = sW2T[c*CH + u];
            const float* yr = &y1s[c*21 + kq*5];
            #pragma unroll
            for (int kk = 0; kk < 5; kk++) h2[kk] = fmaf(w, yr[kk], h2[kk]);
        }
        float mx = h2[0], mn = h2[0];
        #pragma unroll
        for (int kk = 0; kk < 5; kk++) {
            accs += h2[kk]; accq = fmaf(h2[kk], h2[kk], accq);
            mx = fmaxf(mx, h2[kk]); mn = fminf(mn, h2[kk]);
        }
        redm[t] = mx; redn[t] = mn;
        __syncthreads();
        if (kq == 0) {
            float fmx = fmaxf(fmaxf(redm[u], redm[u+64]), fmaxf(redm[u+128], redm[u+192]));
            float fmn = fminf(fminf(redn[u], redn[u+64]), fminf(redn[u+128], redn[u+192]));
            g_hmax[(size_t)p*CH + u] = fmx;
            g_hmin[(size_t)p*CH + u] = fmn;
        }
        __syncthreads();                 // also protects y1s/red reuse
    }
    // BN2 stats block reduction -> double atomics
    redm[t] = accs; redn[t] = accq;
    __syncthreads();
    if (t < CH) {
        atomicAdd(&g_h2sum[t], (double)(redm[t] + redm[t+64] + redm[t+128] + redm[t+192]));
        atomicAdd(&g_h2sq[t],  (double)(redn[t] + redn[t+64] + redn[t+128] + redn[t+192]));
    }
}

// ---------------- F2: finalize BN2 ----------------
__global__ void f2_fold(const float* __restrict__ g2, const float* __restrict__ b2) {
    int o = threadIdx.x; if (o >= CH) return;
    double M = (double)NSAMP;
    double m = g_h2sum[o] / M;
    double v = g_h2sq[o] / M - m*m;
    double a = (double)g2[o] / sqrt(v + BN_EPS);
    g_a2[o] = (float)a;
    g_c2[o] = (float)((double)b2[o] - m*a);
}

// ---------------- K5: BN2+lrelu (via monotone max/min trick) + transpose
__global__ void k5_out(float* __restrict__ out) {
    __shared__ float tile[32][33];
    int b = blockIdx.z;
    int n0 = blockIdx.x*32, o0 = blockIdx.y*32;
    int tx = threadIdx.x, ty = threadIdx.y;
    #pragma unroll
    for (int r = 0; r < 4; r++) {
        int n = n0 + ty + 8*r, o = o0 + tx;
        float a = g_a2[o], c = g_c2[o];
        size_t idx = ((size_t)(b*NPTS + n))*CH + o;
        float h = (a >= 0.f) ? g_hmax[idx] : g_hmin[idx];
        float v = fmaf(a, h, c);
        tile[ty + 8*r][tx] = (v >= 0.f) ? v : SLOPE*v;
    }
    __syncthreads();
    #pragma unroll
    for (int r = 0; r < 4; r++) {
        int o = o0 + ty + 8*r, n = n0 + tx;
        out[((size_t)(b*CH + o))*NPTS + n] = tile[tx][ty + 8*r];
    }
}

// ---------------- launch ----------------
extern "C" void kernel_launch(void* const* d_in, const int* in_sizes, int n_in,
                              void* d_out, int out_size) {
    const float* a  = (const float*)d_in[0];
    const float* W1 = (const float*)d_in[1];
    const float* g1 = (const float*)d_in[2];
    const float* b1 = (const float*)d_in[3];
    const float* W2 = (const float*)d_in[4];
    const float* g2 = (const float*)d_in[5];
    const float* b2 = (const float*)d_in[6];
    float* out = (float*)d_out;

    k0_pack<<<128, 256>>>(a);
    k1_knn<<<512, 64>>>();
    k2_mom<<<512, 256>>>();
    f1_fold<<<1, 64>>>(W1, g1, b1);
    k3_mlp<<<2048, 256>>>(W2);
    f2_fold<<<1, 64>>>(g2, b2);
    k5_out<<<dim3(128, 2, NB), dim3(32, 8)>>>(out);
}

// round 3
// speedup vs baseline: 1.5182x; 1.5156x over previous
#include <cuda_runtime.h>
#include <math_constants.h>
#include <stdint.h>

#define NB    8
#define NPTS  4096
#define KNN   20
#define CH    64
#define NSAMP (NB*NPTS*KNN)      // 655360
#define BN_EPS 1e-5
#define SLOPE  0.2f

// ---------------- device scratch ----------------
__device__ float4 g_packed[NB*NPTS];                 // (x,y,z,|p|^2)
__device__ float  g_E8[(size_t)NSAMP*8];             // edge feats padded to 8
__device__ double g_S1[6];
__device__ double g_S2[21];
__device__ float  g_W1f[CH*6];
__device__ float  g_c1[CH];
__device__ double g_h2sum[CH];
__device__ double g_h2sq[CH];
__device__ float  g_a2[CH], g_c2[CH];
__device__ float  g_hmax[(size_t)NB*NPTS*CH];
__device__ float  g_hmin[(size_t)NB*NPTS*CH];

// ---------------- packed f32x2 helpers ----------------
__device__ __forceinline__ unsigned long long fma2(unsigned long long a,
                                                   unsigned long long b,
                                                   unsigned long long c) {
    unsigned long long d;
    asm("fma.rn.f32x2 %0, %1, %2, %3;" : "=l"(d) : "l"(a), "l"(b), "l"(c));
    return d;
}
__device__ __forceinline__ unsigned long long pack2(float x) {
    unsigned long long d;
    asm("mov.b64 %0, {%1, %1};" : "=l"(d) : "f"(x));
    return d;
}
__device__ __forceinline__ void unpack2(unsigned long long v, float& lo, float& hi) {
    asm("mov.b64 {%0, %1}, %2;" : "=f"(lo), "=f"(hi) : "l"(v));
}

// ---------------- dummy (ncu launch-slot alignment) ----------------
__global__ void kdummy() {}

// ---------------- K0: pack points + zero accumulators ----------------
__global__ void k0_pack(const float* __restrict__ a) {
    int t = blockIdx.x*blockDim.x + threadIdx.x;     // 0..32767
    int b = t / NPTS, n = t % NPTS;
    const float* ab = a + (size_t)b*3*NPTS;
    float x = ab[n], y = ab[NPTS+n], z = ab[2*NPTS+n];
    float sq = fmaf(z,z, fmaf(y,y, x*x));
    g_packed[t] = make_float4(x,y,z,sq);
    if (blockIdx.x == 0) {
        int i = threadIdx.x;
        if (i < 6)  g_S1[i] = 0.0;
        if (i < 21) g_S2[i] = 0.0;
        if (i < CH) { g_h2sum[i] = 0.0; g_h2sq[i] = 0.0; }
    }
}

// ---------------- K1: exact KNN (top-20 smallest d, jax tie order) ------
// d' = sq_j - 2*dot(p_i,p_j)  (constant sq_i dropped: set selection invariant)
// Ascending-index scan with strict '<' reproduces top_k tie-breaking exactly.
__global__ void __launch_bounds__(64) k1_knn() {
    int tid = blockIdx.x*blockDim.x + threadIdx.x;   // 512 blocks x 64
    int b = tid / NPTS; int i = tid % NPTS;
    const float4* pts = &g_packed[b*NPTS];
    float4 pi = pts[i];
    float n2x = -2.f*pi.x, n2y = -2.f*pi.y, n2z = -2.f*pi.z;

    float dl[KNN]; int il[KNN];
    #pragma unroll
    for (int t = 0; t < KNN; t++) { dl[t] = CUDART_INF_F; il[t] = 0; }

    for (int j = 0; j < NPTS; j += 8) {
        float dd[8];
        #pragma unroll
        for (int u = 0; u < 8; u++) {
            float4 pj = __ldg(&pts[j+u]);
            dd[u] = fmaf(n2z, pj.z, fmaf(n2y, pj.y, fmaf(n2x, pj.x, pj.w)));
        }
        #pragma unroll
        for (int u = 0; u < 8; u++) {
            float d = dd[u];
            if (d < dl[KNN-1]) {                     // guarded bubble insert
                int jj = j + u;
                #pragma unroll
                for (int t = 0; t < KNN; t++) {
                    bool p = d < dl[t];
                    float od = dl[t]; int oi = il[t];
                    dl[t] = p ? d  : od;  il[t] = p ? jj : oi;
                    d     = p ? od : d;   jj    = p ? oi : jj;
                }
            }
        }
    }
    // emit edge features [diff(3), pts(3), 0, 0]
    float4* E = (float4*)(g_E8 + (size_t)tid*KNN*8);
    #pragma unroll
    for (int t = 0; t < KNN; t++) {
        float4 pj = pts[il[t]];
        E[t*2+0] = make_float4(pj.x-pi.x, pj.y-pi.y, pj.z-pi.z, pi.x);
        E[t*2+1] = make_float4(pi.y, pi.z, 0.f, 0.f);
    }
}

// ---------------- K2: 1st+2nd moments of edge features ----------------
__global__ void k2_mom() {
    int t = blockIdx.x*blockDim.x + threadIdx.x;     // 512x256 -> 5 samples each
    float s1[6]; float s2[21];
    #pragma unroll
    for (int c = 0; c < 6; c++)  s1[c] = 0.f;
    #pragma unroll
    for (int q = 0; q < 21; q++) s2[q] = 0.f;

    #pragma unroll
    for (int s = 0; s < 5; s++) {
        size_t idx = (size_t)(t*5 + s) * 8;
        float4 v0 = *(const float4*)&g_E8[idx];
        float4 v1 = *(const float4*)&g_E8[idx+4];
        float x[6] = {v0.x, v0.y, v0.z, v0.w, v1.x, v1.y};
        #pragma unroll
        for (int c = 0; c < 6; c++) s1[c] += x[c];
        int q = 0;
        #pragma unroll
        for (int c1 = 0; c1 < 6; c1++)
            #pragma unroll
            for (int c2 = c1; c2 < 6; c2++) { s2[q] = fmaf(x[c1], x[c2], s2[q]); q++; }
    }
    #pragma unroll
    for (int o = 16; o > 0; o >>= 1) {
        #pragma unroll
        for (int c = 0; c < 6; c++)  s1[c] += __shfl_xor_sync(~0u, s1[c], o);
        #pragma unroll
        for (int q = 0; q < 21; q++) s2[q] += __shfl_xor_sync(~0u, s2[q], o);
    }
    if ((threadIdx.x & 31) == 0) {
        #pragma unroll
        for (int c = 0; c < 6; c++)  atomicAdd(&g_S1[c], (double)s1[c]);
        #pragma unroll
        for (int q = 0; q < 21; q++) atomicAdd(&g_S2[q], (double)s2[q]);
    }
}

// ---------------- F1: fold BN1 into W1 ----------------
__global__ void f1_fold(const float* __restrict__ W1, const float* __restrict__ g1,
                        const float* __restrict__ b1) {
    int o = threadIdx.x; if (o >= CH) return;
    double M = (double)NSAMP;
    double m1[6];
    for (int c = 0; c < 6; c++) m1[c] = g_S1[c] / M;
    double E2[6][6]; int q = 0;
    for (int c1 = 0; c1 < 6; c1++)
        for (int c2 = c1; c2 < 6; c2++) { double v = g_S2[q++] / M; E2[c1][c2] = v; E2[c2][c1] = v; }
    double w[6];
    for (int c = 0; c < 6; c++) w[c] = (double)W1[o*6 + c];
    double mean = 0.0;
    for (int c = 0; c < 6; c++) mean += w[c]*m1[c];
    double e2 = 0.0;
    for (int c1 = 0; c1 < 6; c1++) { double acc = 0.0;
        for (int c2 = 0; c2 < 6; c2++) acc += w[c2]*E2[c1][c2];
        e2 += w[c1]*acc; }
    double var = e2 - mean*mean;
    double a = (double)g1[o] / sqrt(var + BN_EPS);
    g_c1[o] = (float)((double)b1[o] - mean*a);
    for (int c = 0; c < 6; c++) g_W1f[o*6 + c] = (float)(a*w[c]);
}

// ---------------- K3: fused MLP (f32x2 packed), BN2 stats, max/min over K
// Block: 256 threads, 16 points via 4 phases of 4 points.
// Phase A: thread (pa, ca) computes y1[pa][ca][k] for k=0..19 (layer1+lrelu).
// Phase B: thread (pb, kq, ug) computes h2 for u in {2ug,2ug+1}, k-pairs
//          kq*10 .. kq*10+9, as 10 packed f32x2 accumulators.
#define YPITCH 22
__global__ void __launch_bounds__(256) k3_mlp(const float* __restrict__ W2) {
    __shared__ float sW2T[CH*CH];          // [c][u]
    __shared__ float y1s[4][CH*YPITCH];    // [p][c*22 + k]
    __shared__ float smx[4][CH], smn[4][CH];
    __shared__ float ssum[CH], ssq[CH];
    int t = threadIdx.x;
    if (t < CH) { ssum[t] = 0.f; ssq[t] = 0.f; }
    for (int s = t; s < CH*CH; s += 256) { int o = s >> 6, c = s & 63; sW2T[c*CH + o] = W2[s]; }

    // phase A identity
    int pa = t >> 6, ca = t & 63;
    float w1r[6];
    #pragma unroll
    for (int c = 0; c < 6; c++) w1r[c] = g_W1f[ca*6 + c];
    float c1v = g_c1[ca];

    // phase B identity
    int r  = t & 63;
    int kq = r >> 5;                       // 0..1  (k-pairs kq*5 .. kq*5+4 -> k kq*10..kq*10+9)
    int ug = r & 31;                       // 0..31
    int u0 = 2*ug, u1 = u0 + 1;
    int k0 = kq * 10;
    float su0 = 0.f, su1 = 0.f, qu0 = 0.f, qu1 = 0.f;
    __syncthreads();

    for (int ph = 0; ph < 4; ph++) {
        int pbase = blockIdx.x*16 + ph*4;
        // ---- phase A: layer1 + lrelu into smem ----
        {
            const float* Ep = g_E8 + (size_t)(pbase + pa)*KNN*8;
            float* yo = &y1s[pa][ca*YPITCH];
            #pragma unroll
            for (int k = 0; k < KNN; k++) {
                float4 v0 = *(const float4*)(Ep + k*8);
                float4 v1 = *(const float4*)(Ep + k*8 + 4);
                float h = c1v;
                h = fmaf(w1r[0], v0.x, h);
                h = fmaf(w1r[1], v0.y, h);
                h = fmaf(w1r[2], v0.z, h);
                h = fmaf(w1r[3], v0.w, h);
                h = fmaf(w1r[4], v1.x, h);
                h = fmaf(w1r[5], v1.y, h);
                yo[k] = (h >= 0.f) ? h : SLOPE*h;
            }
        }
        __syncthreads();
        // ---- phase B: layer2 with packed f32x2 ----
        unsigned long long acc0[5], acc1[5];
        #pragma unroll
        for (int kk = 0; kk < 5; kk++) { acc0[kk] = 0ull; acc1[kk] = 0ull; }
        const float* yb = &y1s[pa][0];
        #pragma unroll 8
        for (int c = 0; c < CH; c++) {
            unsigned long long w0d = pack2(sW2T[c*CH + u0]);
            unsigned long long w1d = pack2(sW2T[c*CH + u1]);
            const float* yr = yb + c*YPITCH + k0;
            #pragma unroll
            for (int kk = 0; kk < 5; kk++) {
                unsigned long long yv = *(const unsigned long long*)(yr + 2*kk);
                acc0[kk] = fma2(w0d, yv, acc0[kk]);
                acc1[kk] = fma2(w1d, yv, acc1[kk]);
            }
        }
        // ---- stats + max/min over this thread's 10 k's ----
        float mx0 = -CUDART_INF_F, mn0 = CUDART_INF_F;
        float mx1 = -CUDART_INF_F, mn1 = CUDART_INF_F;
        #pragma unroll
        for (int kk = 0; kk < 5; kk++) {
            float lo, hi;
            unpack2(acc0[kk], lo, hi);
            su0 += lo + hi; qu0 = fmaf(lo, lo, fmaf(hi, hi, qu0));
            mx0 = fmaxf(mx0, fmaxf(lo, hi)); mn0 = fminf(mn0, fminf(lo, hi));
            unpack2(acc1[kk], lo, hi);
            su1 += lo + hi; qu1 = fmaf(lo, lo, fmaf(hi, hi, qu1));
            mx1 = fmaxf(mx1, fmaxf(lo, hi)); mn1 = fminf(mn1, fminf(lo, hi));
        }
        if (kq == 1) {
            smx[pa][u0] = mx0; smx[pa][u1] = mx1;
            smn[pa][u0] = mn0; smn[pa][u1] = mn1;
        }
        __syncthreads();
        if (kq == 0) {
            size_t o = (size_t)(pbase + pa)*CH;
            g_hmax[o + u0] = fmaxf(mx0, smx[pa][u0]);
            g_hmax[o + u1] = fmaxf(mx1, smx[pa][u1]);
            g_hmin[o + u0] = fminf(mn0, smn[pa][u0]);
            g_hmin[o + u1] = fminf(mn1, smn[pa][u1]);
        }
        __syncthreads();                   // protects y1s/smx reuse next phase
    }
    // BN2 stats: smem float atomics, then 64 global double atomics
    atomicAdd(&ssum[u0], su0); atomicAdd(&ssum[u1], su1);
    atomicAdd(&ssq[u0],  qu0); atomicAdd(&ssq[u1],  qu1);
    __syncthreads();
    if (t < CH) {
        atomicAdd(&g_h2sum[t], (double)ssum[t]);
        atomicAdd(&g_h2sq[t],  (double)ssq[t]);
    }
}

// ---------------- F2: finalize BN2 ----------------
__global__ void f2_fold(const float* __restrict__ g2, const float* __restrict__ b2) {
    int o = threadIdx.x; if (o >= CH) return;
    double M = (double)NSAMP;
    double m = g_h2sum[o] / M;
    double v = g_h2sq[o] / M - m*m;
    double a = (double)g2[o] / sqrt(v + BN_EPS);
    g_a2[o] = (float)a;
    g_c2[o] = (float)((double)b2[o] - m*a);
}

// ---------------- K5: BN2+lrelu via monotone max/min + transpose -------
__global__ void k5_out(float* __restrict__ out) {
    __shared__ float tile[32][33];
    int b = blockIdx.z;
    int n0 = blockIdx.x*32, o0 = blockIdx.y*32;
    int tx = threadIdx.x, ty = threadIdx.y;
    #pragma unroll
    for (int r = 0; r < 4; r++) {
        int n = n0 + ty + 8*r, o = o0 + tx;
        float a = g_a2[o], c = g_c2[o];
        size_t idx = ((size_t)(b*NPTS + n))*CH + o;
        float h = (a >= 0.f) ? g_hmax[idx] : g_hmin[idx];
        float v = fmaf(a, h, c);
        tile[ty + 8*r][tx] = (v >= 0.f) ? v : SLOPE*v;
    }
    __syncthreads();
    #pragma unroll
    for (int r = 0; r < 4; r++) {
        int o = o0 + ty + 8*r, n = n0 + tx;
        out[((size_t)(b*CH + o))*NPTS + n] = tile[tx][ty + 8*r];
    }
}

// ---------------- launch ----------------
extern "C" void kernel_launch(void* const* d_in, const int* in_sizes, int n_in,
                              void* d_out, int out_size) {
    const float* a  = (const float*)d_in[0];
    const float* W1 = (const float*)d_in[1];
    const float* g1 = (const float*)d_in[2];
    const float* b1 = (const float*)d_in[3];
    const float* W2 = (const float*)d_in[4];
    const float* g2 = (const float*)d_in[5];
    const float* b2 = (const float*)d_in[6];
    float* out = (float*)d_out;

    // 4 dummies so ncu (-s 5 -c 1) captures k1_knn next profile
    kdummy<<<1, 32>>>();
    kdummy<<<1, 32>>>();
    kdummy<<<1, 32>>>();
    kdummy<<<1, 32>>>();

    k0_pack<<<128, 256>>>(a);
    k1_knn<<<512, 64>>>();
    k2_mom<<<512, 256>>>();
    f1_fold<<<1, 64>>>(W1, g1, b1);
    k3_mlp<<<2048, 256>>>(W2);
    f2_fold<<<1, 64>>>(g2, b2);
    k5_out<<<dim3(128, 2, NB), dim3(32, 8)>>>(out);
}

// round 4
// speedup vs baseline: 1.6815x; 1.1076x over previous
#include <cuda_runtime.h>
#include <math_constants.h>
#include <stdint.h>

#define NB    8
#define NPTS  4096
#define KNN   20
#define CH    64
#define NSAMP (NB*NPTS*KNN)      // 655360
#define BN_EPS 1e-5
#define SLOPE  0.2f

// ---------------- device scratch ----------------
__device__ float4 g_packed[NB*NPTS];                 // (x,y,z,|p|^2)
__device__ float  g_E8[(size_t)NSAMP*8];             // edge feats padded to 8
__device__ double g_S1[6];
__device__ double g_S2[21];
__device__ float  g_W1f[CH*6];
__device__ float  g_c1[CH];
__device__ double g_h2sum[CH];
__device__ double g_h2sq[CH];
__device__ float  g_a2[CH], g_c2[CH];
__device__ float  g_hmax[(size_t)NB*NPTS*CH];
__device__ float  g_hmin[(size_t)NB*NPTS*CH];

// ---------------- packed f32x2 helpers ----------------
__device__ __forceinline__ unsigned long long fma2(unsigned long long a,
                                                   unsigned long long b,
                                                   unsigned long long c) {
    unsigned long long d;
    asm("fma.rn.f32x2 %0, %1, %2, %3;" : "=l"(d) : "l"(a), "l"(b), "l"(c));
    return d;
}
__device__ __forceinline__ unsigned long long pack2(float x) {
    unsigned long long d;
    asm("mov.b64 %0, {%1, %1};" : "=l"(d) : "f"(x));
    return d;
}
__device__ __forceinline__ void unpack2(unsigned long long v, float& lo, float& hi) {
    asm("mov.b64 {%0, %1}, %2;" : "=f"(lo), "=f"(hi) : "l"(v));
}

// ---------------- dummy (ncu lands on launch index 3 -> k1_knn) --------
__global__ void kdummy() {}

// ---------------- K0: pack points + zero accumulators ----------------
__global__ void k0_pack(const float* __restrict__ a) {
    int t = blockIdx.x*blockDim.x + threadIdx.x;     // 0..32767
    int b = t / NPTS, n = t % NPTS;
    const float* ab = a + (size_t)b*3*NPTS;
    float x = ab[n], y = ab[NPTS+n], z = ab[2*NPTS+n];
    float sq = fmaf(z,z, fmaf(y,y, x*x));
    g_packed[t] = make_float4(x,y,z,sq);
    if (blockIdx.x == 0) {
        int i = threadIdx.x;
        if (i < 6)  g_S1[i] = 0.0;
        if (i < 21) g_S2[i] = 0.0;
        if (i < CH) { g_h2sum[i] = 0.0; g_h2sq[i] = 0.0; }
    }
}

// ---------------- K1: exact KNN, positional (parallel) insert ----------
// d' = sq_j - 2*dot(p_i,p_j); ascending-index scan + strict '<' keeps the
// exact jax top_k tie semantics. Insert uses slot-parallel positional
// update (depth ~12 cyc) instead of a serial carry bubble (depth ~160).
__global__ void __launch_bounds__(64) k1_knn() {
    int tid = blockIdx.x*blockDim.x + threadIdx.x;   // 512 blocks x 64
    int b = tid / NPTS; int i = tid % NPTS;
    const float4* pts = &g_packed[b*NPTS];
    float4 pi = pts[i];
    float n2x = -2.f*pi.x, n2y = -2.f*pi.y, n2z = -2.f*pi.z;

    float dl[KNN]; int il[KNN];
    #pragma unroll
    for (int t = 0; t < KNN; t++) { dl[t] = CUDART_INF_F; il[t] = 0; }

    for (int j = 0; j < NPTS; j += 8) {
        float dd[8];
        #pragma unroll
        for (int u = 0; u < 8; u++) {
            float4 pj = __ldg(&pts[j+u]);
            dd[u] = fmaf(n2z, pj.z, fmaf(n2y, pj.y, fmaf(n2x, pj.x, pj.w)));
        }
        #pragma unroll
        for (int u = 0; u < 8; u++) {
            float d = dd[u];
            if (d < dl[KNN-1]) {
                int jj = j + u;
                // positional insert: all slots update independently.
                // p_t = d < dl[t] is monotone; descending t reads old dl[t-1].
                #pragma unroll
                for (int t = KNN-1; t >= 1; t--) {
                    bool pt  = d < dl[t];
                    bool ptm = d < dl[t-1];
                    dl[t] = pt ? (ptm ? dl[t-1] : d ) : dl[t];
                    il[t] = pt ? (ptm ? il[t-1] : jj) : il[t];
                }
                bool p0 = d < dl[0];
                il[0] = p0 ? jj : il[0];
                dl[0] = p0 ? d  : dl[0];
            }
        }
    }
    // emit edge features [diff(3), pts(3), 0, 0]
    float4* E = (float4*)(g_E8 + (size_t)tid*KNN*8);
    #pragma unroll
    for (int t = 0; t < KNN; t++) {
        float4 pj = pts[il[t]];
        E[t*2+0] = make_float4(pj.x-pi.x, pj.y-pi.y, pj.z-pi.z, pi.x);
        E[t*2+1] = make_float4(pi.y, pi.z, 0.f, 0.f);
    }
}

// ---------------- K2: 1st+2nd moments of edge features ----------------
__global__ void k2_mom() {
    int t = blockIdx.x*blockDim.x + threadIdx.x;     // 512x256 -> 5 samples each
    float s1[6]; float s2[21];
    #pragma unroll
    for (int c = 0; c < 6; c++)  s1[c] = 0.f;
    #pragma unroll
    for (int q = 0; q < 21; q++) s2[q] = 0.f;

    #pragma unroll
    for (int s = 0; s < 5; s++) {
        size_t idx = (size_t)(t*5 + s) * 8;
        float4 v0 = *(const float4*)&g_E8[idx];
        float4 v1 = *(const float4*)&g_E8[idx+4];
        float x[6] = {v0.x, v0.y, v0.z, v0.w, v1.x, v1.y};
        #pragma unroll
        for (int c = 0; c < 6; c++) s1[c] += x[c];
        int q = 0;
        #pragma unroll
        for (int c1 = 0; c1 < 6; c1++)
            #pragma unroll
            for (int c2 = c1; c2 < 6; c2++) { s2[q] = fmaf(x[c1], x[c2], s2[q]); q++; }
    }
    #pragma unroll
    for (int o = 16; o > 0; o >>= 1) {
        #pragma unroll
        for (int c = 0; c < 6; c++)  s1[c] += __shfl_xor_sync(~0u, s1[c], o);
        #pragma unroll
        for (int q = 0; q < 21; q++) s2[q] += __shfl_xor_sync(~0u, s2[q], o);
    }
    if ((threadIdx.x & 31) == 0) {
        #pragma unroll
        for (int c = 0; c < 6; c++)  atomicAdd(&g_S1[c], (double)s1[c]);
        #pragma unroll
        for (int q = 0; q < 21; q++) atomicAdd(&g_S2[q], (double)s2[q]);
    }
}

// ---------------- F1: fold BN1 into W1 ----------------
__global__ void f1_fold(const float* __restrict__ W1, const float* __restrict__ g1,
                        const float* __restrict__ b1) {
    int o = threadIdx.x; if (o >= CH) return;
    double M = (double)NSAMP;
    double m1[6];
    for (int c = 0; c < 6; c++) m1[c] = g_S1[c] / M;
    double E2[6][6]; int q = 0;
    for (int c1 = 0; c1 < 6; c1++)
        for (int c2 = c1; c2 < 6; c2++) { double v = g_S2[q++] / M; E2[c1][c2] = v; E2[c2][c1] = v; }
    double w[6];
    for (int c = 0; c < 6; c++) w[c] = (double)W1[o*6 + c];
    double mean = 0.0;
    for (int c = 0; c < 6; c++) mean += w[c]*m1[c];
    double e2 = 0.0;
    for (int c1 = 0; c1 < 6; c1++) { double acc = 0.0;
        for (int c2 = 0; c2 < 6; c2++) acc += w[c2]*E2[c1][c2];
        e2 += w[c1]*acc; }
    double var = e2 - mean*mean;
    double a = (double)g1[o] / sqrt(var + BN_EPS);
    g_c1[o] = (float)((double)b1[o] - mean*a);
    for (int c = 0; c < 6; c++) g_W1f[o*6 + c] = (float)(a*w[c]);
}

// ---------------- K3: fused MLP (f32x2 packed), BN2 stats, max/min over K
#define YPITCH 22
__global__ void __launch_bounds__(256) k3_mlp(const float* __restrict__ W2) {
    __shared__ float sW2T[CH*CH];          // [c][u]
    __shared__ float y1s[4][CH*YPITCH];    // [p][c*22 + k]
    __shared__ float smx[4][CH], smn[4][CH];
    __shared__ float ssum[CH], ssq[CH];
    int t = threadIdx.x;
    if (t < CH) { ssum[t] = 0.f; ssq[t] = 0.f; }
    for (int s = t; s < CH*CH; s += 256) { int o = s >> 6, c = s & 63; sW2T[c*CH + o] = W2[s]; }

    // phase A identity
    int pa = t >> 6, ca = t & 63;
    float w1r[6];
    #pragma unroll
    for (int c = 0; c < 6; c++) w1r[c] = g_W1f[ca*6 + c];
    float c1v = g_c1[ca];

    // phase B identity
    int r  = t & 63;
    int kq = r >> 5;                       // warp-uniform
    int ug = r & 31;
    int u0 = 2*ug, u1 = u0 + 1;
    int k0 = kq * 10;
    float su0 = 0.f, su1 = 0.f, qu0 = 0.f, qu1 = 0.f;
    __syncthreads();

    for (int ph = 0; ph < 4; ph++) {
        int pbase = blockIdx.x*16 + ph*4;
        // ---- phase A: layer1 + lrelu into smem ----
        {
            const float* Ep = g_E8 + (size_t)(pbase + pa)*KNN*8;
            float* yo = &y1s[pa][ca*YPITCH];
            #pragma unroll
            for (int k = 0; k < KNN; k++) {
                float4 v0 = *(const float4*)(Ep + k*8);
                float4 v1 = *(const float4*)(Ep + k*8 + 4);
                float h = c1v;
                h = fmaf(w1r[0], v0.x, h);
                h = fmaf(w1r[1], v0.y, h);
                h = fmaf(w1r[2], v0.z, h);
                h = fmaf(w1r[3], v0.w, h);
                h = fmaf(w1r[4], v1.x, h);
                h = fmaf(w1r[5], v1.y, h);
                yo[k] = (h >= 0.f) ? h : SLOPE*h;
            }
        }
        __syncthreads();
        // ---- phase B: layer2 with packed f32x2 ----
        unsigned long long acc0[5], acc1[5];
        #pragma unroll
        for (int kk = 0; kk < 5; kk++) { acc0[kk] = 0ull; acc1[kk] = 0ull; }
        const float* yb = &y1s[pa][0];
        #pragma unroll 8
        for (int c = 0; c < CH; c++) {
            float2 wp = *(const float2*)&sW2T[c*CH + u0];   // one LDS.64
            unsigned long long w0d = pack2(wp.x);
            unsigned long long w1d = pack2(wp.y);
            const float* yr = yb + c*YPITCH + k0;
            #pragma unroll
            for (int kk = 0; kk < 5; kk++) {
                unsigned long long yv = *(const unsigned long long*)(yr + 2*kk);
                acc0[kk] = fma2(w0d, yv, acc0[kk]);
                acc1[kk] = fma2(w1d, yv, acc1[kk]);
            }
        }
        // ---- stats + max/min over this thread's 10 k's ----
        float mx0 = -CUDART_INF_F, mn0 = CUDART_INF_F;
        float mx1 = -CUDART_INF_F, mn1 = CUDART_INF_F;
        #pragma unroll
        for (int kk = 0; kk < 5; kk++) {
            float lo, hi;
            unpack2(acc0[kk], lo, hi);
            su0 += lo + hi; qu0 = fmaf(lo, lo, fmaf(hi, hi, qu0));
            mx0 = fmaxf(mx0, fmaxf(lo, hi)); mn0 = fminf(mn0, fminf(lo, hi));
            unpack2(acc1[kk], lo, hi);
            su1 += lo + hi; qu1 = fmaf(lo, lo, fmaf(hi, hi, qu1));
            mx1 = fmaxf(mx1, fmaxf(lo, hi)); mn1 = fminf(mn1, fminf(lo, hi));
        }
        if (kq == 1) {
            smx[pa][u0] = mx0; smx[pa][u1] = mx1;
            smn[pa][u0] = mn0; smn[pa][u1] = mn1;
        }
        __syncthreads();
        if (kq == 0) {
            size_t o = (size_t)(pbase + pa)*CH;
            g_hmax[o + u0] = fmaxf(mx0, smx[pa][u0]);
            g_hmax[o + u1] = fmaxf(mx1, smx[pa][u1]);
            g_hmin[o + u0] = fminf(mn0, smn[pa][u0]);
            g_hmin[o + u1] = fminf(mn1, smn[pa][u1]);
        }
        __syncthreads();
    }
    // BN2 stats
    atomicAdd(&ssum[u0], su0); atomicAdd(&ssum[u1], su1);
    atomicAdd(&ssq[u0],  qu0); atomicAdd(&ssq[u1],  qu1);
    __syncthreads();
    if (t < CH) {
        atomicAdd(&g_h2sum[t], (double)ssum[t]);
        atomicAdd(&g_h2sq[t],  (double)ssq[t]);
    }
}

// ---------------- F2: finalize BN2 ----------------
__global__ void f2_fold(const float* __restrict__ g2, const float* __restrict__ b2) {
    int o = threadIdx.x; if (o >= CH) return;
    double M = (double)NSAMP;
    double m = g_h2sum[o] / M;
    double v = g_h2sq[o] / M - m*m;
    double a = (double)g2[o] / sqrt(v + BN_EPS);
    g_a2[o] = (float)a;
    g_c2[o] = (float)((double)b2[o] - m*a);
}

// ---------------- K5: BN2+lrelu via monotone max/min + transpose -------
__global__ void k5_out(float* __restrict__ out) {
    __shared__ float tile[32][33];
    int b = blockIdx.z;
    int n0 = blockIdx.x*32, o0 = blockIdx.y*32;
    int tx = threadIdx.x, ty = threadIdx.y;
    #pragma unroll
    for (int r = 0; r < 4; r++) {
        int n = n0 + ty + 8*r, o = o0 + tx;
        float a = g_a2[o], c = g_c2[o];
        size_t idx = ((size_t)(b*NPTS + n))*CH + o;
        float h = (a >= 0.f) ? g_hmax[idx] : g_hmin[idx];
        float v = fmaf(a, h, c);
        tile[ty + 8*r][tx] = (v >= 0.f) ? v : SLOPE*v;
    }
    __syncthreads();
    #pragma unroll
    for (int r = 0; r < 4; r++) {
        int o = o0 + ty + 8*r, n = n0 + tx;
        out[((size_t)(b*CH + o))*NPTS + n] = tile[tx][ty + 8*r];
    }
}

// ---------------- launch ----------------
extern "C" void kernel_launch(void* const* d_in, const int* in_sizes, int n_in,
                              void* d_out, int out_size) {
    const float* a  = (const float*)d_in[0];
    const float* W1 = (const float*)d_in[1];
    const float* g1 = (const float*)d_in[2];
    const float* b1 = (const float*)d_in[3];
    const float* W2 = (const float*)d_in[4];
    const float* g2 = (const float*)d_in[5];
    const float* b2 = (const float*)d_in[6];
    float* out = (float*)d_out;

    // 2 dummies: ncu capture lands on launch index 3 == k1_knn
    kdummy<<<1, 32>>>();
    kdummy<<<1, 32>>>();

    k0_pack<<<128, 256>>>(a);       // index 2
    k1_knn<<<512, 64>>>();          // index 3  <- profiled
    k2_mom<<<512, 256>>>();
    f1_fold<<<1, 64>>>(W1, g1, b1);
    k3_mlp<<<2048, 256>>>(W2);
    f2_fold<<<1, 64>>>(g2, b2);
    k5_out<<<dim3(128, 2, NB), dim3(32, 8)>>>(out);
}

// round 5
// speedup vs baseline: 1.7115x; 1.0178x over previous
#include <cuda_runtime.h>
#include <math_constants.h>
#include <stdint.h>

#define NB    8
#define NPTS  4096
#define KNN   20
#define CH    64
#define NSAMP (NB*NPTS*KNN)      // 655360
#define NQ    (NB*NPTS)          // 32768 queries
#define NSEG  2
#define SEGN  (NPTS/NSEG)        // 2048
#define BN_EPS 1e-5
#define SLOPE  0.2f

// ---------------- device scratch ----------------
__device__ float4 g_packed[NB*NPTS];                 // (x,y,z,|p|^2)
__device__ float  g_E8[(size_t)NSAMP*8];             // edge feats padded to 8
__device__ float  g_dl[NSEG*NQ*KNN];                 // per-segment sorted dists
__device__ int    g_il[NSEG*NQ*KNN];                 // per-segment sorted idx
__device__ double g_S1[6];
__device__ double g_S2[21];
__device__ float  g_W1f[CH*6];
__device__ float  g_c1[CH];
__device__ double g_h2sum[CH];
__device__ double g_h2sq[CH];
__device__ float  g_a2[CH], g_c2[CH];
__device__ float  g_hmax[(size_t)NB*NPTS*CH];
__device__ float  g_hmin[(size_t)NB*NPTS*CH];

// ---------------- packed f32x2 helpers ----------------
__device__ __forceinline__ unsigned long long fma2(unsigned long long a,
                                                   unsigned long long b,
                                                   unsigned long long c) {
    unsigned long long d;
    asm("fma.rn.f32x2 %0, %1, %2, %3;" : "=l"(d) : "l"(a), "l"(b), "l"(c));
    return d;
}
__device__ __forceinline__ unsigned long long pack2(float x) {
    unsigned long long d;
    asm("mov.b64 %0, {%1, %1};" : "=l"(d) : "f"(x));
    return d;
}
__device__ __forceinline__ void unpack2(unsigned long long v, float& lo, float& hi) {
    asm("mov.b64 {%0, %1}, %2;" : "=f"(lo), "=f"(hi) : "l"(v));
}

// ---------------- dummy (ncu lands on launch index 3 -> k1_seg) --------
__global__ void kdummy() {}

// ---------------- K0: pack points + zero accumulators ----------------
__global__ void k0_pack(const float* __restrict__ a) {
    int t = blockIdx.x*blockDim.x + threadIdx.x;     // 0..32767
    int b = t / NPTS, n = t % NPTS;
    const float* ab = a + (size_t)b*3*NPTS;
    float x = ab[n], y = ab[NPTS+n], z = ab[2*NPTS+n];
    float sq = fmaf(z,z, fmaf(y,y, x*x));
    g_packed[t] = make_float4(x,y,z,sq);
    if (blockIdx.x == 0) {
        int i = threadIdx.x;
        if (i < 6)  g_S1[i] = 0.0;
        if (i < 21) g_S2[i] = 0.0;
        if (i < CH) { g_h2sum[i] = 0.0; g_h2sq[i] = 0.0; }
    }
}

// ---------------- K1a: segmented KNN scan (2048 candidates / thread) ----
// grid 1024 x 64: blocks [0,512) = segment 0, [512,1024) = segment 1.
// d' = sq_j - 2*dot(p_i,p_j); ascending-index scan + strict '<' keeps the
// per-segment list lexicographically sorted by (d, j).
__global__ void __launch_bounds__(64) k1_seg() {
    int blk = blockIdx.x;
    int seg = (blk >= 512) ? 1 : 0;
    int qid = (blk & 511)*64 + threadIdx.x;          // 0..32767
    int b = qid / NPTS; int i = qid % NPTS;
    const float4* pts = &g_packed[b*NPTS];
    float4 pi = pts[i];
    float n2x = -2.f*pi.x, n2y = -2.f*pi.y, n2z = -2.f*pi.z;

    float dl[KNN]; int il[KNN];
    #pragma unroll
    for (int t = 0; t < KNN; t++) { dl[t] = CUDART_INF_F; il[t] = 0; }

    int jbase = seg * SEGN;
    for (int j = 0; j < SEGN; j += 8) {
        float dd[8];
        #pragma unroll
        for (int u = 0; u < 8; u++) {
            float4 pj = __ldg(&pts[jbase + j + u]);
            dd[u] = fmaf(n2z, pj.z, fmaf(n2y, pj.y, fmaf(n2x, pj.x, pj.w)));
        }
        #pragma unroll
        for (int u = 0; u < 8; u++) {
            float d = dd[u];
            if (d < dl[KNN-1]) {
                int jj = jbase + j + u;
                // slot-parallel positional insert (shallow dep depth)
                #pragma unroll
                for (int t = KNN-1; t >= 1; t--) {
                    bool pt  = d < dl[t];
                    bool ptm = d < dl[t-1];
                    dl[t] = pt ? (ptm ? dl[t-1] : d ) : dl[t];
                    il[t] = pt ? (ptm ? il[t-1] : jj) : il[t];
                }
                bool p0 = d < dl[0];
                il[0] = p0 ? jj : il[0];
                dl[0] = p0 ? d  : dl[0];
            }
        }
    }
    size_t o = ((size_t)seg*NQ + qid)*KNN;
    #pragma unroll
    for (int t = 0; t < KNN; t++) { g_dl[o+t] = dl[t]; g_il[o+t] = il[t]; }
}

// ---------------- K1b: merge 2 sorted lists (exact lex order) + emit E8 -
__global__ void __launch_bounds__(256) k1_merge() {
    int qid = blockIdx.x*blockDim.x + threadIdx.x;   // 0..32767
    int b = qid / NPTS; int i = qid % NPTS;
    const float4* pts = &g_packed[b*NPTS];
    float4 pi = pts[i];

    const float* dA = &g_dl[(size_t)qid*KNN];
    const int*   iA = &g_il[(size_t)qid*KNN];
    const float* dB = &g_dl[((size_t)NQ + qid)*KNN];
    const int*   iB = &g_il[((size_t)NQ + qid)*KNN];

    float4* E = (float4*)(g_E8 + (size_t)qid*KNN*8);
    int ia = 0, ib = 0;
    float da = dA[0], db = dB[0];
    #pragma unroll
    for (int t = 0; t < KNN; t++) {
        // seg0 indices are all < seg1 indices, so da <= db is exact
        // lexicographic (d, j) preference.
        bool takeA = (da <= db);
        int jj = takeA ? iA[ia] : iB[ib];
        float4 pj = pts[jj];
        E[t*2+0] = make_float4(pj.x-pi.x, pj.y-pi.y, pj.z-pi.z, pi.x);
        E[t*2+1] = make_float4(pi.y, pi.z, 0.f, 0.f);
        if (takeA) { ia++; da = (ia < KNN) ? dA[ia] : CUDART_INF_F; }
        else       { ib++; db = (ib < KNN) ? dB[ib] : CUDART_INF_F; }
    }
}

// ---------------- K2: 1st+2nd moments of edge features ----------------
__global__ void k2_mom() {
    int t = blockIdx.x*blockDim.x + threadIdx.x;     // 512x256 -> 5 samples each
    float s1[6]; float s2[21];
    #pragma unroll
    for (int c = 0; c < 6; c++)  s1[c] = 0.f;
    #pragma unroll
    for (int q = 0; q < 21; q++) s2[q] = 0.f;

    #pragma unroll
    for (int s = 0; s < 5; s++) {
        size_t idx = (size_t)(t*5 + s) * 8;
        float4 v0 = *(const float4*)&g_E8[idx];
        float4 v1 = *(const float4*)&g_E8[idx+4];
        float x[6] = {v0.x, v0.y, v0.z, v0.w, v1.x, v1.y};
        #pragma unroll
        for (int c = 0; c < 6; c++) s1[c] += x[c];
        int q = 0;
        #pragma unroll
        for (int c1 = 0; c1 < 6; c1++)
            #pragma unroll
            for (int c2 = c1; c2 < 6; c2++) { s2[q] = fmaf(x[c1], x[c2], s2[q]); q++; }
    }
    #pragma unroll
    for (int o = 16; o > 0; o >>= 1) {
        #pragma unroll
        for (int c = 0; c < 6; c++)  s1[c] += __shfl_xor_sync(~0u, s1[c], o);
        #pragma unroll
        for (int q = 0; q < 21; q++) s2[q] += __shfl_xor_sync(~0u, s2[q], o);
    }
    if ((threadIdx.x & 31) == 0) {
        #pragma unroll
        for (int c = 0; c < 6; c++)  atomicAdd(&g_S1[c], (double)s1[c]);
        #pragma unroll
        for (int q = 0; q < 21; q++) atomicAdd(&g_S2[q], (double)s2[q]);
    }
}

// ---------------- F1: fold BN1 into W1 ----------------
__global__ void f1_fold(const float* __restrict__ W1, const float* __restrict__ g1,
                        const float* __restrict__ b1) {
    int o = threadIdx.x; if (o >= CH) return;
    double M = (double)NSAMP;
    double m1[6];
    for (int c = 0; c < 6; c++) m1[c] = g_S1[c] / M;
    double E2[6][6]; int q = 0;
    for (int c1 = 0; c1 < 6; c1++)
        for (int c2 = c1; c2 < 6; c2++) { double v = g_S2[q++] / M; E2[c1][c2] = v; E2[c2][c1] = v; }
    double w[6];
    for (int c = 0; c < 6; c++) w[c] = (double)W1[o*6 + c];
    double mean = 0.0;
    for (int c = 0; c < 6; c++) mean += w[c]*m1[c];
    double e2 = 0.0;
    for (int c1 = 0; c1 < 6; c1++) { double acc = 0.0;
        for (int c2 = 0; c2 < 6; c2++) acc += w[c2]*E2[c1][c2];
        e2 += w[c1]*acc; }
    double var = e2 - mean*mean;
    double a = (double)g1[o] / sqrt(var + BN_EPS);
    g_c1[o] = (float)((double)b1[o] - mean*a);
    for (int c = 0; c < 6; c++) g_W1f[o*6 + c] = (float)(a*w[c]);
}

// ---------------- K3: fused MLP (f32x2 packed), BN2 stats, max/min over K
#define YPITCH 22
__global__ void __launch_bounds__(256) k3_mlp(const float* __restrict__ W2) {
    __shared__ float sW2T[CH*CH];          // [c][u]
    __shared__ float y1s[4][CH*YPITCH];    // [p][c*22 + k]
    __shared__ float smx[4][CH], smn[4][CH];
    __shared__ float ssum[CH], ssq[CH];
    int t = threadIdx.x;
    if (t < CH) { ssum[t] = 0.f; ssq[t] = 0.f; }
    for (int s = t; s < CH*CH; s += 256) { int o = s >> 6, c = s & 63; sW2T[c*CH + o] = W2[s]; }

    int pa = t >> 6, ca = t & 63;
    float w1r[6];
    #pragma unroll
    for (int c = 0; c < 6; c++) w1r[c] = g_W1f[ca*6 + c];
    float c1v = g_c1[ca];

    int r  = t & 63;
    int kq = r >> 5;
    int ug = r & 31;
    int u0 = 2*ug, u1 = u0 + 1;
    int k0 = kq * 10;
    float su0 = 0.f, su1 = 0.f, qu0 = 0.f, qu1 = 0.f;
    __syncthreads();

    for (int ph = 0; ph < 4; ph++) {
        int pbase = blockIdx.x*16 + ph*4;
        {
            const float* Ep = g_E8 + (size_t)(pbase + pa)*KNN*8;
            float* yo = &y1s[pa][ca*YPITCH];
            #pragma unroll
            for (int k = 0; k < KNN; k++) {
                float4 v0 = *(const float4*)(Ep + k*8);
                float4 v1 = *(const float4*)(Ep + k*8 + 4);
                float h = c1v;
                h = fmaf(w1r[0], v0.x, h);
                h = fmaf(w1r[1], v0.y, h);
                h = fmaf(w1r[2], v0.z, h);
                h = fmaf(w1r[3], v0.w, h);
                h = fmaf(w1r[4], v1.x, h);
                h = fmaf(w1r[5], v1.y, h);
                yo[k] = (h >= 0.f) ? h : SLOPE*h;
            }
        }
        __syncthreads();
        unsigned long long acc0[5], acc1[5];
        #pragma unroll
        for (int kk = 0; kk < 5; kk++) { acc0[kk] = 0ull; acc1[kk] = 0ull; }
        const float* yb = &y1s[pa][0];
        #pragma unroll 8
        for (int c = 0; c < CH; c++) {
            float2 wp = *(const float2*)&sW2T[c*CH + u0];
            unsigned long long w0d = pack2(wp.x);
            unsigned long long w1d = pack2(wp.y);
            const float* yr = yb + c*YPITCH + k0;
            #pragma unroll
            for (int kk = 0; kk < 5; kk++) {
                unsigned long long yv = *(const unsigned long long*)(yr + 2*kk);
                acc0[kk] = fma2(w0d, yv, acc0[kk]);
                acc1[kk] = fma2(w1d, yv, acc1[kk]);
            }
        }
        float mx0 = -CUDART_INF_F, mn0 = CUDART_INF_F;
        float mx1 = -CUDART_INF_F, mn1 = CUDART_INF_F;
        #pragma unroll
        for (int kk = 0; kk < 5; kk++) {
            float lo, hi;
            unpack2(acc0[kk], lo, hi);
            su0 += lo + hi; qu0 = fmaf(lo, lo, fmaf(hi, hi, qu0));
            mx0 = fmaxf(mx0, fmaxf(lo, hi)); mn0 = fminf(mn0, fminf(lo, hi));
            unpack2(acc1[kk], lo, hi);
            su1 += lo + hi; qu1 = fmaf(lo, lo, fmaf(hi, hi, qu1));
            mx1 = fmaxf(mx1, fmaxf(lo, hi)); mn1 = fminf(mn1, fminf(lo, hi));
        }
        if (kq == 1) {
            smx[pa][u0] = mx0; smx[pa][u1] = mx1;
            smn[pa][u0] = mn0; smn[pa][u1] = mn1;
        }
        __syncthreads();
        if (kq == 0) {
            size_t o = (size_t)(pbase + pa)*CH;
            g_hmax[o + u0] = fmaxf(mx0, smx[pa][u0]);
            g_hmax[o + u1] = fmaxf(mx1, smx[pa][u1]);
            g_hmin[o + u0] = fminf(mn0, smn[pa][u0]);
            g_hmin[o + u1] = fminf(mn1, smn[pa][u1]);
        }
        __syncthreads();
    }
    atomicAdd(&ssum[u0], su0); atomicAdd(&ssum[u1], su1);
    atomicAdd(&ssq[u0],  qu0); atomicAdd(&ssq[u1],  qu1);
    __syncthreads();
    if (t < CH) {
        atomicAdd(&g_h2sum[t], (double)ssum[t]);
        atomicAdd(&g_h2sq[t],  (double)ssq[t]);
    }
}

// ---------------- F2: finalize BN2 ----------------
__global__ void f2_fold(const float* __restrict__ g2, const float* __restrict__ b2) {
    int o = threadIdx.x; if (o >= CH) return;
    double M = (double)NSAMP;
    double m = g_h2sum[o] / M;
    double v = g_h2sq[o] / M - m*m;
    double a = (double)g2[o] / sqrt(v + BN_EPS);
    g_a2[o] = (float)a;
    g_c2[o] = (float)((double)b2[o] - m*a);
}

// ---------------- K5: BN2+lrelu via monotone max/min + transpose -------
__global__ void k5_out(float* __restrict__ out) {
    __shared__ float tile[32][33];
    int b = blockIdx.z;
    int n0 = blockIdx.x*32, o0 = blockIdx.y*32;
    int tx = threadIdx.x, ty = threadIdx.y;
    #pragma unroll
    for (int r = 0; r < 4; r++) {
        int n = n0 + ty + 8*r, o = o0 + tx;
        float a = g_a2[o], c = g_c2[o];
        size_t idx = ((size_t)(b*NPTS + n))*CH + o;
        float h = (a >= 0.f) ? g_hmax[idx] : g_hmin[idx];
        float v = fmaf(a, h, c);
        tile[ty + 8*r][tx] = (v >= 0.f) ? v : SLOPE*v;
    }
    __syncthreads();
    #pragma unroll
    for (int r = 0; r < 4; r++) {
        int o = o0 + ty + 8*r, n = n0 + tx;
        out[((size_t)(b*CH + o))*NPTS + n] = tile[tx][ty + 8*r];
    }
}

// ---------------- launch ----------------
extern "C" void kernel_launch(void* const* d_in, const int* in_sizes, int n_in,
                              void* d_out, int out_size) {
    const float* a  = (const float*)d_in[0];
    const float* W1 = (const float*)d_in[1];
    const float* g1 = (const float*)d_in[2];
    const float* b1 = (const float*)d_in[3];
    const float* W2 = (const float*)d_in[4];
    const float* g2 = (const float*)d_in[5];
    const float* b2 = (const float*)d_in[6];
    float* out = (float*)d_out;

    // 2 dummies: ncu capture lands on launch index 3 == k1_seg
    kdummy<<<1, 32>>>();
    kdummy<<<1, 32>>>();

    k0_pack<<<128, 256>>>(a);        // index 2
    k1_seg<<<1024, 64>>>();          // index 3  <- profiled
    k1_merge<<<128, 256>>>();
    k2_mom<<<512, 256>>>();
    f1_fold<<<1, 64>>>(W1, g1, b1);
    k3_mlp<<<2048, 256>>>(W2);
    f2_fold<<<1, 64>>>(g2, b2);
    k5_out<<<dim3(128, 2, NB), dim3(32, 8)>>>(out);
}